// round 1
// baseline (speedup 1.0000x reference)
#include <cuda_runtime.h>
#include <cuda_bf16.h>
#include <cstdint>
#include <cmath>

// Problem constants: B=4, S=4096, E=1024, H=16, hd=64
#define TOK     16384            // B*S
#define EDIM    1024
#define NHEAD   16
#define HDIM    64
#define BH      64               // B*H
#define SEQ     4096
#define EPSN    1e-4f

// ---------------- scratch (static device memory; no allocations) -----------
__device__ float g_wn[4u * 1024u * 1024u];          // 4 normalized weights, 16 MB
__device__ float g_q[(size_t)TOK * EDIM];           // 64 MB
__device__ float g_k[(size_t)TOK * EDIM];           // 64 MB
__device__ float g_v[(size_t)TOK * EDIM];           // 64 MB
__device__ float g_o[(size_t)TOK * EDIM];           // 64 MB
__device__ float g_scp[4u * BH * HDIM * HDIM];      // partial scores (s-split), 4 MB
__device__ float g_attn[BH * HDIM * HDIM];          // softmaxed attn, 1 MB

// ---------------- 1) magnitude-preserving weight normalization -------------
// wn[row,:] = w[row,:] * (gain/32) / (1e-4 + ||w[row,:]||/32)      (sqrt(1024)=32)
__global__ __launch_bounds__(256)
void norm_weights_kernel(const float* __restrict__ wq, const float* __restrict__ wk,
                         const float* __restrict__ wv, const float* __restrict__ wo,
                         const float* __restrict__ gain_p)
{
    int row = blockIdx.x;          // 0..1023
    int mat = blockIdx.y;          // 0..3
    const float* W = (mat == 0) ? wq : (mat == 1) ? wk : (mat == 2) ? wv : wo;
    const float* src = W + (size_t)row * EDIM;

    int tid = threadIdx.x;
    float4 w4 = *(const float4*)(src + tid * 4);
    float ss = w4.x * w4.x + w4.y * w4.y + w4.z * w4.z + w4.w * w4.w;

    // block reduction
    __shared__ float red[8];
    int lane = tid & 31, warp = tid >> 5;
    #pragma unroll
    for (int o = 16; o > 0; o >>= 1) ss += __shfl_xor_sync(0xffffffffu, ss, o);
    if (lane == 0) red[warp] = ss;
    __syncthreads();
    if (tid == 0) {
        float t = 0.f;
        #pragma unroll
        for (int i = 0; i < 8; i++) t += red[i];
        red[0] = t;
    }
    __syncthreads();
    float total = red[0];
    float g = *gain_p;
    float scale = (g * (1.0f / 32.0f)) / (EPSN + sqrtf(total) * (1.0f / 32.0f));

    float* dst = g_wn + (size_t)mat * (1024u * 1024u) + (size_t)row * EDIM + tid * 4;
    float4 out4 = make_float4(w4.x * scale, w4.y * scale, w4.z * scale, w4.w * scale);
    *(float4*)dst = out4;
}

// ---------------- 2) SGEMM: C[M,N] = A[M,K] * B[N,K]^T  (+ optional residual epilogue)
// M=16384, N=1024, K=1024. 128x128x8 tiles, 256 threads, 8x8 micro-tiles.
__global__ __launch_bounds__(256)
void sgemm_nt_kernel(const float* __restrict__ A, const float* __restrict__ B,
                     float* __restrict__ C, const float* __restrict__ Res, float alpha)
{
    const int K = EDIM, N = EDIM;
    __shared__ float As[8][128];
    __shared__ float Bs[8][128];

    int tid = threadIdx.x;
    int bm = blockIdx.y * 128;
    int bn = blockIdx.x * 128;

    // global->smem loader mapping: 256 threads load 128x8 tile (1 float4 each)
    int lrow = tid >> 1;            // 0..127
    int lcol = (tid & 1) * 4;       // 0 or 4

    // warp tiling: 8 warps as 4(rows) x 2(cols), lanes 4x8, 8x8 per-thread tile
    int warp = tid >> 5, lane = tid & 31;
    int wr = warp & 3, wc = warp >> 2;
    int rbase = wr * 32 + (lane >> 3) * 8;   // row offset in tile
    int cbase = wc * 64 + (lane & 7) * 8;    // col offset in tile

    float acc[8][8];
    #pragma unroll
    for (int i = 0; i < 8; i++)
        #pragma unroll
        for (int j = 0; j < 8; j++) acc[i][j] = 0.f;

    const float* Aptr = A + (size_t)(bm + lrow) * K + lcol;
    const float* Bptr = B + (size_t)(bn + lrow) * K + lcol;

    for (int k0 = 0; k0 < K; k0 += 8) {
        float4 a = *(const float4*)(Aptr + k0);
        float4 b = *(const float4*)(Bptr + k0);
        As[lcol + 0][lrow] = a.x; As[lcol + 1][lrow] = a.y;
        As[lcol + 2][lrow] = a.z; As[lcol + 3][lrow] = a.w;
        Bs[lcol + 0][lrow] = b.x; Bs[lcol + 1][lrow] = b.y;
        Bs[lcol + 2][lrow] = b.z; Bs[lcol + 3][lrow] = b.w;
        __syncthreads();

        #pragma unroll
        for (int kk = 0; kk < 8; kk++) {
            float ar[8], br[8];
            *(float4*)(ar)     = *(const float4*)&As[kk][rbase];
            *(float4*)(ar + 4) = *(const float4*)&As[kk][rbase + 4];
            *(float4*)(br)     = *(const float4*)&Bs[kk][cbase];
            *(float4*)(br + 4) = *(const float4*)&Bs[kk][cbase + 4];
            #pragma unroll
            for (int i = 0; i < 8; i++)
                #pragma unroll
                for (int j = 0; j < 8; j++)
                    acc[i][j] = fmaf(ar[i], br[j], acc[i][j]);
        }
        __syncthreads();
    }

    // epilogue
    #pragma unroll
    for (int i = 0; i < 8; i++) {
        size_t row = (size_t)(bm + rbase + i);
        float* Cp = C + row * N + bn + cbase;
        if (Res != nullptr) {
            const float* Rp = Res + row * N + bn + cbase;
            #pragma unroll
            for (int j = 0; j < 8; j++)
                Cp[j] = (acc[i][j] + Rp[j]) * alpha;
        } else {
            #pragma unroll
            for (int j = 0; j < 8; j++)
                Cp[j] = acc[i][j];
        }
    }
}

// ---------------- 3) per-head normalization of q and k ---------------------
// x / (1e-4 + ||x||/8) per (token, head) over 64 contiguous elements
__global__ __launch_bounds__(512)
void norm_qk_kernel()
{
    int t = blockIdx.x;                       // token 0..16383
    float* buf = (blockIdx.y == 0) ? g_q : g_k;
    int warp = threadIdx.x >> 5;              // head 0..15
    int lane = threadIdx.x & 31;
    size_t base = (size_t)t * EDIM + warp * HDIM;
    float a = buf[base + lane];
    float b = buf[base + 32 + lane];
    float ss = a * a + b * b;
    #pragma unroll
    for (int o = 16; o > 0; o >>= 1) ss += __shfl_xor_sync(0xffffffffu, ss, o);
    float inv = 1.0f / (EPSN + sqrtf(ss) * 0.125f);
    buf[base + lane] = a * inv;
    buf[base + 32 + lane] = b * inv;
}

// ---------------- 4) partial scores: scores[bn,h,k] = sum_s qn[s,h]*kn[s,k] -
// s split into 4 chunks of 1024; block = one (b,h) pair x one chunk
__global__ __launch_bounds__(256)
void scores_part_kernel()
{
    int bn = blockIdx.x;      // 0..63  (b*16 + n)
    int chunk = blockIdx.y;   // 0..3
    int b = bn >> 4, n = bn & 15;

    __shared__ float qs[32][64];
    __shared__ float ks[32][64];

    int tid = threadIdx.x;
    int ty = tid >> 4, tx = tid & 15;

    float acc[4][4];
    #pragma unroll
    for (int i = 0; i < 4; i++)
        #pragma unroll
        for (int j = 0; j < 4; j++) acc[i][j] = 0.f;

    size_t tbase = ((size_t)b * SEQ + (size_t)chunk * 1024) * EDIM + n * HDIM;

    for (int s0 = 0; s0 < 1024; s0 += 32) {
        #pragma unroll
        for (int r = 0; r < 2; r++) {
            int f = tid + r * 256;            // 0..511 float4s
            int rr = f >> 4;                  // 0..31
            int cc = (f & 15) * 4;            // 0..60
            size_t g = tbase + (size_t)(s0 + rr) * EDIM + cc;
            *(float4*)&qs[rr][cc] = *(const float4*)&g_q[g];
            *(float4*)&ks[rr][cc] = *(const float4*)&g_k[g];
        }
        __syncthreads();

        #pragma unroll 4
        for (int ss = 0; ss < 32; ss++) {
            float4 q4 = *(const float4*)&qs[ss][ty * 4];
            float4 k4 = *(const float4*)&ks[ss][tx * 4];
            float qa[4] = {q4.x, q4.y, q4.z, q4.w};
            float ka[4] = {k4.x, k4.y, k4.z, k4.w};
            #pragma unroll
            for (int i = 0; i < 4; i++)
                #pragma unroll
                for (int j = 0; j < 4; j++)
                    acc[i][j] = fmaf(qa[i], ka[j], acc[i][j]);
        }
        __syncthreads();
    }

    #pragma unroll
    for (int i = 0; i < 4; i++)
        #pragma unroll
        for (int j = 0; j < 4; j++)
            g_scp[(((size_t)chunk * BH + bn) * HDIM + ty * 4 + i) * HDIM + tx * 4 + j] = acc[i][j];
}

// ---------------- 5) softmax over k (rows of length 64), fold 1/sqrt(S) ----
__global__ __launch_bounds__(256)
void softmax_kernel()
{
    int gw = blockIdx.x * 8 + (threadIdx.x >> 5);   // global warp 0..4095
    int lane = threadIdx.x & 31;
    int bn = gw >> 6, h = gw & 63;

    float v0 = 0.f, v1 = 0.f;
    #pragma unroll
    for (int c = 0; c < 4; c++) {
        size_t o = (((size_t)c * BH + bn) * HDIM + h) * HDIM;
        v0 += g_scp[o + lane];
        v1 += g_scp[o + 32 + lane];
    }
    v0 *= (1.0f / 64.0f);   // 1/sqrt(4096)
    v1 *= (1.0f / 64.0f);

    float m = fmaxf(v0, v1);
    #pragma unroll
    for (int o = 16; o > 0; o >>= 1) m = fmaxf(m, __shfl_xor_sync(0xffffffffu, m, o));
    float e0 = __expf(v0 - m), e1 = __expf(v1 - m);
    float s = e0 + e1;
    #pragma unroll
    for (int o = 16; o > 0; o >>= 1) s += __shfl_xor_sync(0xffffffffu, s, o);
    float inv = 1.0f / s;

    size_t idx = ((size_t)bn * HDIM + h) * HDIM;
    g_attn[idx + lane] = e0 * inv;
    g_attn[idx + 32 + lane] = e1 * inv;
}

// ---------------- 6) apply attention: o[s,h] = sum_k attn[h,k] * v[s,k] -----
// block = one (b,head) x 64-token tile
__global__ __launch_bounds__(256)
void o_apply_kernel()
{
    int bn = blockIdx.x;          // 0..63
    int st = blockIdx.y;          // 0..63 (64-token tile)
    int b = bn >> 4, n = bn & 15;

    __shared__ float at[64 * 65];   // attn transposed [k][h], pad 65
    __shared__ float vt[64 * 65];   // v transposed    [k][s], pad 65

    int tid = threadIdx.x;
    size_t abase = (size_t)bn * HDIM * HDIM;
    #pragma unroll
    for (int r = 0; r < 16; r++) {
        int e = tid + r * 256;            // 0..4095
        int h = e >> 6, k = e & 63;
        at[k * 65 + h] = g_attn[abase + e];
    }
    size_t vbase = ((size_t)b * SEQ + (size_t)st * 64) * EDIM + n * HDIM;
    #pragma unroll
    for (int r = 0; r < 16; r++) {
        int e = tid + r * 256;
        int s = e >> 6, k = e & 63;
        vt[k * 65 + s] = g_v[vbase + (size_t)s * EDIM + k];
    }
    __syncthreads();

    int ty = tid >> 4, tx = tid & 15;
    int s0 = ty * 4, h0 = tx * 4;
    float acc[4][4];
    #pragma unroll
    for (int i = 0; i < 4; i++)
        #pragma unroll
        for (int j = 0; j < 4; j++) acc[i][j] = 0.f;

    #pragma unroll 4
    for (int k = 0; k < 64; k++) {
        float av[4], vv[4];
        #pragma unroll
        for (int j = 0; j < 4; j++) av[j] = at[k * 65 + h0 + j];
        #pragma unroll
        for (int i = 0; i < 4; i++) vv[i] = vt[k * 65 + s0 + i];
        #pragma unroll
        for (int i = 0; i < 4; i++)
            #pragma unroll
            for (int j = 0; j < 4; j++)
                acc[i][j] = fmaf(av[j], vv[i], acc[i][j]);
    }

    size_t obase = ((size_t)b * SEQ + (size_t)st * 64) * EDIM + n * HDIM;
    #pragma unroll
    for (int i = 0; i < 4; i++)
        #pragma unroll
        for (int j = 0; j < 4; j++)
            g_o[obase + (size_t)(s0 + i) * EDIM + h0 + j] = acc[i][j];
}

// ---------------- host launcher --------------------------------------------
extern "C" void kernel_launch(void* const* d_in, const int* in_sizes, int n_in,
                              void* d_out, int out_size)
{
    const float* query = (const float*)d_in[0];
    const float* gain  = (const float*)d_in[1];
    const float* wq    = (const float*)d_in[2];
    const float* wk    = (const float*)d_in[3];
    const float* wv    = (const float*)d_in[4];
    const float* wo    = (const float*)d_in[5];
    float* out = (float*)d_out;

    float *p_wn, *p_q, *p_k, *p_v, *p_o;
    cudaGetSymbolAddress((void**)&p_wn, g_wn);
    cudaGetSymbolAddress((void**)&p_q,  g_q);
    cudaGetSymbolAddress((void**)&p_k,  g_k);
    cudaGetSymbolAddress((void**)&p_v,  g_v);
    cudaGetSymbolAddress((void**)&p_o,  g_o);

    // 1) normalize the 4 weight matrices
    norm_weights_kernel<<<dim3(1024, 4), 256>>>(wq, wk, wv, wo, gain);

    // 2) Q/K/V projections
    dim3 ggrid(EDIM / 128, TOK / 128);   // (8, 128)
    sgemm_nt_kernel<<<ggrid, 256>>>(query, p_wn + 0u * (1024u * 1024u), p_q, nullptr, 1.0f);
    sgemm_nt_kernel<<<ggrid, 256>>>(query, p_wn + 1u * (1024u * 1024u), p_k, nullptr, 1.0f);
    sgemm_nt_kernel<<<ggrid, 256>>>(query, p_wn + 2u * (1024u * 1024u), p_v, nullptr, 1.0f);

    // 3) per-head normalize q, k
    norm_qk_kernel<<<dim3(TOK, 2), 512>>>();

    // 4) partial scores over s-chunks
    scores_part_kernel<<<dim3(BH, 4), 256>>>();

    // 5) reduce + softmax
    softmax_kernel<<<512, 256>>>();

    // 6) apply attention weights to v
    o_apply_kernel<<<dim3(BH, 64), 256>>>();

    // 7) output projection + residual mix: (res + proj) * sqrt(0.5)
    sgemm_nt_kernel<<<ggrid, 256>>>(p_o, p_wn + 3u * (1024u * 1024u), out, query, 0.70710678118654752f);
}

// round 3
// speedup vs baseline: 3.3189x; 3.3189x over previous
#include <cuda_runtime.h>
#include <cuda_bf16.h>
#include <cstdint>
#include <cmath>

// Problem constants: B=4, S=4096, E=1024, H=16, hd=64
#define TOK     16384            // B*S
#define EDIM    1024
#define NHEAD   16
#define HDIM    64
#define BH      64               // B*H
#define SEQ     4096
#define EPSN    1e-4f

// ---------------- scratch (static device memory; no allocations) -----------
__device__ float g_wn[4u * 1024u * 1024u];          // 4 normalized weights (tf32-rounded)
__device__ float g_qt[(size_t)TOK * EDIM];          // query, tf32-rounded
__device__ float g_q[(size_t)TOK * EDIM];
__device__ float g_k[(size_t)TOK * EDIM];
__device__ float g_v[(size_t)TOK * EDIM];
__device__ float g_o[(size_t)TOK * EDIM];           // attn output, tf32-rounded
__device__ float g_scp[4u * BH * HDIM * HDIM];      // partial scores (s-split)
__device__ float g_attn[BH * HDIM * HDIM];          // softmaxed attn

// ======================= PTX helpers ========================================
__device__ __forceinline__ uint32_t smem_to_u32(const void* p) {
    uint32_t a;
    asm("{ .reg .u64 t; cvta.to.shared.u64 t, %1; cvt.u32.u64 %0, t; }" : "=r"(a) : "l"(p));
    return a;
}
__device__ __forceinline__ float to_tf32(float x) {
    float r;
    asm("cvt.rna.tf32.f32 %0, %1;" : "=f"(r) : "f"(x));
    return r;
}

#define CP_ASYNC16(dst, src) \
    asm volatile("cp.async.cg.shared.global [%0], [%1], 16;" :: "r"(dst), "l"(src))
#define CP_COMMIT()  asm volatile("cp.async.commit_group;" ::: "memory")
#define CP_WAIT2()   asm volatile("cp.async.wait_group 2;" ::: "memory")

// m16n8k8 tf32 MMA (arch-portable; lowers to fallback HMMA on sm_103)
__device__ __forceinline__ void mma_tf32(float* d, const uint32_t* a, const uint32_t* b) {
    asm volatile(
        "mma.sync.aligned.m16n8k8.row.col.f32.tf32.tf32.f32 "
        "{%0,%1,%2,%3}, {%4,%5,%6,%7}, {%8,%9}, {%0,%1,%2,%3};"
        : "+f"(d[0]), "+f"(d[1]), "+f"(d[2]), "+f"(d[3])
        : "r"(a[0]), "r"(a[1]), "r"(a[2]), "r"(a[3]), "r"(b[0]), "r"(b[1]));
}

// ======================= tf32 mma.sync GEMM =================================
// C[16384,1024] = A[16384,1024(K)] * B[1024,1024(K)]^T   (row-major, K contiguous)
// 128x128 CTA tile, K-chunk 32 floats, 3-stage cp.async pipeline.
// 8 warps = 2(M) x 4(N); warp tile 64x32 via 4x4 m16n8k8 fragments.
#define PADW   36                       // floats per smem row (32 + 4 pad)
#define STAGEF (128 * PADW)             // 4608 floats per stage tile
#define GEMM_SMEM_BYTES (6 * STAGEF * 4)  // A:3 stages + B:3 stages = 110592

__global__ __launch_bounds__(256)
void gemm_tc_kernel(const float* __restrict__ A, const float* __restrict__ B,
                    float* __restrict__ C, const float* __restrict__ Res, float alpha)
{
    extern __shared__ __align__(16) float smem[];
    float* sA0 = smem;                  // 3 stages of A
    float* sB0 = smem + 3 * STAGEF;     // 3 stages of B
    const uint32_t sbaseA = smem_to_u32(sA0);
    const uint32_t sbaseB = smem_to_u32(sB0);

    const int tid = threadIdx.x;
    const int wid = tid >> 5;
    const int lane = tid & 31;
    const int g = lane >> 2;            // group id 0..7
    const int tig = lane & 3;           // thread-in-group 0..3
    const int m0 = (wid >> 2) * 64;     // warp M offset in tile
    const int n0 = (wid & 3) * 32;      // warp N offset in tile
    const int bm = blockIdx.y * 128;
    const int bn = blockIdx.x * 128;

    const char* gA = (const char*)(A + (size_t)bm * EDIM);
    const char* gB = (const char*)(B + (size_t)bn * EDIM);

    // loader: one K-chunk (128 rows x 32 floats) of A and B into stage st
    auto load_chunk = [&](int kc, int st) {
        uint32_t dA = sbaseA + (uint32_t)st * (STAGEF * 4);
        uint32_t dB = sbaseB + (uint32_t)st * (STAGEF * 4);
        int koff = kc * 128;                 // byte offset of chunk within row
        #pragma unroll
        for (int r = 0; r < 4; r++) {
            int f = tid + r * 256;           // 0..1023 float4 slots
            int row = f >> 3;                // 0..127
            int seg = (f & 7) * 16;          // byte seg within chunk row
            uint32_t so = (uint32_t)(row * (PADW * 4) + seg);
            size_t  go = (size_t)row * (EDIM * 4) + koff + seg;
            CP_ASYNC16(dA + so, gA + go);
            CP_ASYNC16(dB + so, gB + go);
        }
    };

    float acc[4][4][4];
    #pragma unroll
    for (int i = 0; i < 4; i++)
        #pragma unroll
        for (int j = 0; j < 4; j++)
            #pragma unroll
            for (int r = 0; r < 4; r++) acc[i][j][r] = 0.f;

    // prologue: 2 chunks in flight
    load_chunk(0, 0); CP_COMMIT();
    load_chunk(1, 1); CP_COMMIT();

    for (int c = 0; c < 32; c++) {
        // issue next load first (stage safety: trailing __syncthreads of iter c-1)
        if (c + 2 < 32) load_chunk(c + 2, (c + 2) % 3);
        CP_COMMIT();                      // always commit (maybe empty group)
        CP_WAIT2();                       // chunk c's group complete
        __syncthreads();

        const uint32_t* As = (const uint32_t*)(sA0 + (c % 3) * STAGEF);
        const uint32_t* Bs = (const uint32_t*)(sB0 + (c % 3) * STAGEF);

        #pragma unroll
        for (int ks = 0; ks < 4; ks++) {
            int kb = ks * 8 + tig;
            uint32_t a[4][4];
            #pragma unroll
            for (int i = 0; i < 4; i++) {
                int r0 = m0 + 16 * i + g;
                a[i][0] = As[r0 * PADW + kb];
                a[i][1] = As[(r0 + 8) * PADW + kb];
                a[i][2] = As[r0 * PADW + kb + 4];
                a[i][3] = As[(r0 + 8) * PADW + kb + 4];
            }
            uint32_t b[4][2];
            #pragma unroll
            for (int j = 0; j < 4; j++) {
                int rn = n0 + 8 * j + g;
                b[j][0] = Bs[rn * PADW + kb];
                b[j][1] = Bs[rn * PADW + kb + 4];
            }
            #pragma unroll
            for (int i = 0; i < 4; i++)
                #pragma unroll
                for (int j = 0; j < 4; j++)
                    mma_tf32(acc[i][j], a[i], b[j]);
        }
        __syncthreads();
    }

    // epilogue: c0,c1 -> (row, col..col+1); c2,c3 -> (row+8, ...)
    #pragma unroll
    for (int i = 0; i < 4; i++) {
        int row = bm + m0 + 16 * i + g;
        #pragma unroll
        for (int j = 0; j < 4; j++) {
            int col = bn + n0 + 8 * j + tig * 2;
            float2 v0 = make_float2(acc[i][j][0], acc[i][j][1]);
            float2 v1 = make_float2(acc[i][j][2], acc[i][j][3]);
            if (Res != nullptr) {
                float2 r0 = *(const float2*)(Res + (size_t)row * EDIM + col);
                float2 r1 = *(const float2*)(Res + (size_t)(row + 8) * EDIM + col);
                v0.x = (v0.x + r0.x) * alpha; v0.y = (v0.y + r0.y) * alpha;
                v1.x = (v1.x + r1.x) * alpha; v1.y = (v1.y + r1.y) * alpha;
            }
            *(float2*)(C + (size_t)row * EDIM + col) = v0;
            *(float2*)(C + (size_t)(row + 8) * EDIM + col) = v1;
        }
    }
}

// ---------------- tf32 RNA convert (query) ---------------------------------
__global__ __launch_bounds__(256)
void tf32_convert_kernel(const float* __restrict__ in, float* __restrict__ out)
{
    size_t i = (size_t)(blockIdx.x * 256 + threadIdx.x) * 4;
    float4 v = *(const float4*)(in + i);
    v.x = to_tf32(v.x); v.y = to_tf32(v.y); v.z = to_tf32(v.z); v.w = to_tf32(v.w);
    *(float4*)(out + i) = v;
}

// ---------------- magnitude-preserving weight normalization (-> tf32) ------
__global__ __launch_bounds__(256)
void norm_weights_kernel(const float* __restrict__ wq, const float* __restrict__ wk,
                         const float* __restrict__ wv, const float* __restrict__ wo,
                         const float* __restrict__ gain_p)
{
    int row = blockIdx.x;
    int mat = blockIdx.y;
    const float* W = (mat == 0) ? wq : (mat == 1) ? wk : (mat == 2) ? wv : wo;
    const float* src = W + (size_t)row * EDIM;

    int tid = threadIdx.x;
    float4 w4 = *(const float4*)(src + tid * 4);
    float ss = w4.x * w4.x + w4.y * w4.y + w4.z * w4.z + w4.w * w4.w;

    __shared__ float red[8];
    int lane = tid & 31, warp = tid >> 5;
    #pragma unroll
    for (int o = 16; o > 0; o >>= 1) ss += __shfl_xor_sync(0xffffffffu, ss, o);
    if (lane == 0) red[warp] = ss;
    __syncthreads();
    if (tid == 0) {
        float t = 0.f;
        #pragma unroll
        for (int i = 0; i < 8; i++) t += red[i];
        red[0] = t;
    }
    __syncthreads();
    float scale = (*gain_p * (1.0f / 32.0f)) / (EPSN + sqrtf(red[0]) * (1.0f / 32.0f));

    float* dst = g_wn + (size_t)mat * (1024u * 1024u) + (size_t)row * EDIM + tid * 4;
    *(float4*)dst = make_float4(to_tf32(w4.x * scale), to_tf32(w4.y * scale),
                                to_tf32(w4.z * scale), to_tf32(w4.w * scale));
}

// ---------------- per-head normalization of q and k -------------------------
__global__ __launch_bounds__(512)
void norm_qk_kernel()
{
    int t = blockIdx.x;
    float* buf = (blockIdx.y == 0) ? g_q : g_k;
    int warp = threadIdx.x >> 5;
    int lane = threadIdx.x & 31;
    size_t base = (size_t)t * EDIM + warp * HDIM;
    float a = buf[base + lane];
    float b = buf[base + 32 + lane];
    float ss = a * a + b * b;
    #pragma unroll
    for (int o = 16; o > 0; o >>= 1) ss += __shfl_xor_sync(0xffffffffu, ss, o);
    float inv = 1.0f / (EPSN + sqrtf(ss) * 0.125f);
    buf[base + lane] = a * inv;
    buf[base + 32 + lane] = b * inv;
}

// ---------------- partial scores: scores[bn,h,k] = sum_s qn[s,h]*kn[s,k] ----
__global__ __launch_bounds__(256)
void scores_part_kernel()
{
    int bn = blockIdx.x;
    int chunk = blockIdx.y;
    int b = bn >> 4, n = bn & 15;

    __shared__ float qs[32][64];
    __shared__ float ks[32][64];

    int tid = threadIdx.x;
    int ty = tid >> 4, tx = tid & 15;

    float acc[4][4];
    #pragma unroll
    for (int i = 0; i < 4; i++)
        #pragma unroll
        for (int j = 0; j < 4; j++) acc[i][j] = 0.f;

    size_t tbase = ((size_t)b * SEQ + (size_t)chunk * 1024) * EDIM + n * HDIM;

    for (int s0 = 0; s0 < 1024; s0 += 32) {
        #pragma unroll
        for (int r = 0; r < 2; r++) {
            int f = tid + r * 256;
            int rr = f >> 4;
            int cc = (f & 15) * 4;
            size_t gg = tbase + (size_t)(s0 + rr) * EDIM + cc;
            *(float4*)&qs[rr][cc] = *(const float4*)&g_q[gg];
            *(float4*)&ks[rr][cc] = *(const float4*)&g_k[gg];
        }
        __syncthreads();

        #pragma unroll 4
        for (int ss = 0; ss < 32; ss++) {
            float4 q4 = *(const float4*)&qs[ss][ty * 4];
            float4 k4 = *(const float4*)&ks[ss][tx * 4];
            float qa[4] = {q4.x, q4.y, q4.z, q4.w};
            float ka[4] = {k4.x, k4.y, k4.z, k4.w};
            #pragma unroll
            for (int i = 0; i < 4; i++)
                #pragma unroll
                for (int j = 0; j < 4; j++)
                    acc[i][j] = fmaf(qa[i], ka[j], acc[i][j]);
        }
        __syncthreads();
    }

    #pragma unroll
    for (int i = 0; i < 4; i++)
        #pragma unroll
        for (int j = 0; j < 4; j++)
            g_scp[(((size_t)chunk * BH + bn) * HDIM + ty * 4 + i) * HDIM + tx * 4 + j] = acc[i][j];
}

// ---------------- softmax over k (rows of length 64) ------------------------
__global__ __launch_bounds__(256)
void softmax_kernel()
{
    int gw = blockIdx.x * 8 + (threadIdx.x >> 5);
    int lane = threadIdx.x & 31;
    int bn = gw >> 6, h = gw & 63;

    float v0 = 0.f, v1 = 0.f;
    #pragma unroll
    for (int c = 0; c < 4; c++) {
        size_t o = (((size_t)c * BH + bn) * HDIM + h) * HDIM;
        v0 += g_scp[o + lane];
        v1 += g_scp[o + 32 + lane];
    }
    v0 *= (1.0f / 64.0f);
    v1 *= (1.0f / 64.0f);

    float m = fmaxf(v0, v1);
    #pragma unroll
    for (int o = 16; o > 0; o >>= 1) m = fmaxf(m, __shfl_xor_sync(0xffffffffu, m, o));
    float e0 = __expf(v0 - m), e1 = __expf(v1 - m);
    float s = e0 + e1;
    #pragma unroll
    for (int o = 16; o > 0; o >>= 1) s += __shfl_xor_sync(0xffffffffu, s, o);
    float inv = 1.0f / s;

    size_t idx = ((size_t)bn * HDIM + h) * HDIM;
    g_attn[idx + lane] = e0 * inv;
    g_attn[idx + 32 + lane] = e1 * inv;
}

// ---------------- apply attention: o[s,h] = sum_k attn[h,k] * v[s,k] --------
__global__ __launch_bounds__(256)
void o_apply_kernel()
{
    int bn = blockIdx.x;
    int st = blockIdx.y;
    int b = bn >> 4, n = bn & 15;

    __shared__ float at[64 * 65];
    __shared__ float vt[64 * 65];

    int tid = threadIdx.x;
    size_t abase = (size_t)bn * HDIM * HDIM;
    #pragma unroll
    for (int r = 0; r < 16; r++) {
        int e = tid + r * 256;
        int h = e >> 6, k = e & 63;
        at[k * 65 + h] = g_attn[abase + e];
    }
    size_t vbase = ((size_t)b * SEQ + (size_t)st * 64) * EDIM + n * HDIM;
    #pragma unroll
    for (int r = 0; r < 16; r++) {
        int e = tid + r * 256;
        int s = e >> 6, k = e & 63;
        vt[k * 65 + s] = g_v[vbase + (size_t)s * EDIM + k];
    }
    __syncthreads();

    int ty = tid >> 4, tx = tid & 15;
    int s0 = ty * 4, h0 = tx * 4;
    float acc[4][4];
    #pragma unroll
    for (int i = 0; i < 4; i++)
        #pragma unroll
        for (int j = 0; j < 4; j++) acc[i][j] = 0.f;

    #pragma unroll 4
    for (int k = 0; k < 64; k++) {
        float av[4], vv[4];
        #pragma unroll
        for (int j = 0; j < 4; j++) av[j] = at[k * 65 + h0 + j];
        #pragma unroll
        for (int i = 0; i < 4; i++) vv[i] = vt[k * 65 + s0 + i];
        #pragma unroll
        for (int i = 0; i < 4; i++)
            #pragma unroll
            for (int j = 0; j < 4; j++)
                acc[i][j] = fmaf(av[j], vv[i], acc[i][j]);
    }

    size_t obase = ((size_t)b * SEQ + (size_t)st * 64) * EDIM + n * HDIM;
    #pragma unroll
    for (int i = 0; i < 4; i++)
        #pragma unroll
        for (int j = 0; j < 4; j++)
            g_o[obase + (size_t)(s0 + i) * EDIM + h0 + j] = to_tf32(acc[i][j]);
}

// ---------------- host launcher --------------------------------------------
extern "C" void kernel_launch(void* const* d_in, const int* in_sizes, int n_in,
                              void* d_out, int out_size)
{
    const float* query = (const float*)d_in[0];
    const float* gain  = (const float*)d_in[1];
    const float* wq    = (const float*)d_in[2];
    const float* wk    = (const float*)d_in[3];
    const float* wv    = (const float*)d_in[4];
    const float* wo    = (const float*)d_in[5];
    float* out = (float*)d_out;

    float *p_wn, *p_qt, *p_q, *p_k, *p_v, *p_o;
    cudaGetSymbolAddress((void**)&p_wn, g_wn);
    cudaGetSymbolAddress((void**)&p_qt, g_qt);
    cudaGetSymbolAddress((void**)&p_q,  g_q);
    cudaGetSymbolAddress((void**)&p_k,  g_k);
    cudaGetSymbolAddress((void**)&p_v,  g_v);
    cudaGetSymbolAddress((void**)&p_o,  g_o);

    cudaFuncSetAttribute(gemm_tc_kernel,
                         cudaFuncAttributeMaxDynamicSharedMemorySize, GEMM_SMEM_BYTES);

    // 1) normalize weights (tf32-rounded), convert query to tf32
    norm_weights_kernel<<<dim3(1024, 4), 256>>>(wq, wk, wv, wo, gain);
    tf32_convert_kernel<<<TOK * EDIM / 1024, 256>>>(query, p_qt);

    // 2) Q/K/V projections on tensor cores (mma.sync tf32)
    dim3 ggrid(EDIM / 128, TOK / 128);   // (8, 128)
    gemm_tc_kernel<<<ggrid, 256, GEMM_SMEM_BYTES>>>(p_qt, p_wn + 0u * (1024u * 1024u), p_q, nullptr, 1.0f);
    gemm_tc_kernel<<<ggrid, 256, GEMM_SMEM_BYTES>>>(p_qt, p_wn + 1u * (1024u * 1024u), p_k, nullptr, 1.0f);
    gemm_tc_kernel<<<ggrid, 256, GEMM_SMEM_BYTES>>>(p_qt, p_wn + 2u * (1024u * 1024u), p_v, nullptr, 1.0f);

    // 3) per-head normalize q, k
    norm_qk_kernel<<<dim3(TOK, 2), 512>>>();

    // 4) partial scores over s-chunks
    scores_part_kernel<<<dim3(BH, 4), 256>>>();

    // 5) reduce + softmax
    softmax_kernel<<<512, 256>>>();

    // 6) apply attention weights to v (writes tf32-rounded)
    o_apply_kernel<<<dim3(BH, 64), 256>>>();

    // 7) output projection + residual mix: (res + proj) * sqrt(0.5)
    gemm_tc_kernel<<<ggrid, 256, GEMM_SMEM_BYTES>>>(p_o, p_wn + 3u * (1024u * 1024u), out, query, 0.70710678118654752f);
}